// round 14
// baseline (speedup 1.0000x reference)
#include <cuda_runtime.h>
#include <cuda_bf16.h>
#include <math.h>
#include <stdint.h>

#define BATCH 2
#define SEQ   4096
#define DMODEL 768
#define NHEAD 12
#define HDIM  64
#define NTOK  (BATCH*SEQ)   // 8192

// ---------------- scratch (no allocations allowed) ----------------
__device__ __nv_bfloat16 g_qhi[(size_t)BATCH*NHEAD*SEQ*HDIM];  // [B,H,S,64], pre-scaled 1/8
__device__ __nv_bfloat16 g_qlo[(size_t)BATCH*NHEAD*SEQ*HDIM];
__device__ __nv_bfloat16 g_khi[(size_t)BATCH*NHEAD*SEQ*HDIM];
__device__ __nv_bfloat16 g_klo[(size_t)BATCH*NHEAD*SEQ*HDIM];
__device__ __nv_bfloat16 g_vhi[(size_t)BATCH*NHEAD*SEQ*HDIM];
__device__ __nv_bfloat16 g_vlo[(size_t)BATCH*NHEAD*SEQ*HDIM];

__device__ __nv_bfloat16 g_xhi[(size_t)NTOK*DMODEL];   // x splits; later reused for preout splits
__device__ __nv_bfloat16 g_xlo[(size_t)NTOK*DMODEL];
__device__ __nv_bfloat16 g_whi[4*(size_t)DMODEL*DMODEL];
__device__ __nv_bfloat16 g_wlo[4*(size_t)DMODEL*DMODEL];

// ================= portable (sm_80+) asm helpers =================
__device__ __forceinline__ uint32_t smem_u32(const void* p){
    uint32_t a;
    asm("{ .reg .u64 t; cvta.to.shared.u64 t, %1; cvt.u32.u64 %0, t; }" : "=r"(a) : "l"(p));
    return a;
}

#define CP_ASYNC16(dst, src) \
    asm volatile("cp.async.cg.shared.global [%0], [%1], 16;" :: "r"(dst), "l"(src))
#define CP_COMMIT()  asm volatile("cp.async.commit_group;" ::: "memory")
#define CP_WAIT0()   asm volatile("cp.async.wait_group 0;" ::: "memory")
#define CP_WAIT1()   asm volatile("cp.async.wait_group 1;" ::: "memory")

#define LDSM4(r, addr) \
    asm volatile("ldmatrix.sync.aligned.m8n8.x4.shared.b16 {%0,%1,%2,%3}, [%4];" \
        : "=r"((r)[0]), "=r"((r)[1]), "=r"((r)[2]), "=r"((r)[3]) : "r"(addr))

#define LDSM4T(r, addr) \
    asm volatile("ldmatrix.sync.aligned.m8n8.x4.trans.shared.b16 {%0,%1,%2,%3}, [%4];" \
        : "=r"((r)[0]), "=r"((r)[1]), "=r"((r)[2]), "=r"((r)[3]) : "r"(addr))

#define MMA_BF16(d, a, b0, b1) \
    asm volatile("mma.sync.aligned.m16n8k16.row.col.f32.bf16.bf16.f32 " \
        "{%0,%1,%2,%3}, {%4,%5,%6,%7}, {%8,%9}, {%0,%1,%2,%3};" \
        : "+f"((d)[0]), "+f"((d)[1]), "+f"((d)[2]), "+f"((d)[3]) \
        : "r"((a)[0]), "r"((a)[1]), "r"((a)[2]), "r"((a)[3]), "r"(b0), "r"(b1))

__device__ __forceinline__ uint32_t packbf(float lo, float hi){
    uint32_t r;
    asm("cvt.rn.bf16x2.f32 %0, %1, %2;" : "=r"(r) : "f"(hi), "f"(lo));
    return r;
}
__device__ __forceinline__ float lo16f(uint32_t p){ return __uint_as_float(p << 16); }
__device__ __forceinline__ float hi16f(uint32_t p){ return __uint_as_float(p & 0xffff0000u); }

// =================================================================
// split kernels
// =================================================================
__global__ void split_kernel(const float* __restrict__ in,
                             __nv_bfloat16* __restrict__ hi,
                             __nv_bfloat16* __restrict__ lo, int n4)
{
    int i = blockIdx.x * blockDim.x + threadIdx.x;
    if (i >= n4) return;
    float4 v = ((const float4*)in)[i];
    uint32_t h0 = packbf(v.x, v.y);
    uint32_t h1 = packbf(v.z, v.w);
    uint32_t l0 = packbf(v.x - lo16f(h0), v.y - hi16f(h0));
    uint32_t l1 = packbf(v.z - lo16f(h1), v.w - hi16f(h1));
    ((uint32_t*)hi)[2*i]   = h0;
    ((uint32_t*)hi)[2*i+1] = h1;
    ((uint32_t*)lo)[2*i]   = l0;
    ((uint32_t*)lo)[2*i+1] = l1;
}

// fused 4-weight split: blockIdx.y selects matrix; outputs at mat*WSZ
__global__ void split_w4_kernel(const float* __restrict__ w0, const float* __restrict__ w1,
                                const float* __restrict__ w2, const float* __restrict__ w3,
                                int n4)
{
    int i = blockIdx.x * blockDim.x + threadIdx.x;
    if (i >= n4) return;
    int mat = blockIdx.y;
    const float* in = (mat == 0) ? w0 : (mat == 1) ? w1 : (mat == 2) ? w2 : w3;
    const size_t WSZ = (size_t)DMODEL * DMODEL;
    __nv_bfloat16* hi = g_whi + (size_t)mat * WSZ;
    __nv_bfloat16* lo = g_wlo + (size_t)mat * WSZ;
    float4 v = ((const float4*)in)[i];
    uint32_t h0 = packbf(v.x, v.y);
    uint32_t h1 = packbf(v.z, v.w);
    uint32_t l0 = packbf(v.x - lo16f(h0), v.y - hi16f(h0));
    uint32_t l1 = packbf(v.z - lo16f(h1), v.w - hi16f(h1));
    ((uint32_t*)hi)[2*i]   = h0;
    ((uint32_t*)hi)[2*i+1] = h1;
    ((uint32_t*)lo)[2*i]   = l0;
    ((uint32_t*)lo)[2*i+1] = l1;
}

// =================================================================
// GEMM core machinery (shared by QKV-fused and out-proj kernels)
// CTA tile 128x64, 8 warps (4m x 2n), K-chunks of 64, 2-stage pipe.
// =================================================================
#define GKC 64
#define NKCH (DMODEL/GKC)          // 12
#define APITCH_B 144

#define SG_AHI 0
#define SG_ALO 18432
#define SG_BHI 36864
#define SG_BLO 46080
#define GEMM_STAGE 55296
#define GEMM_SMEM  (2*GEMM_STAGE)  // 110592

struct GemmAcc { float a[2][4][4]; };

__device__ __forceinline__ void gemm_load_stage(
    uint32_t st, int tid, int row0, int col0, int k0,
    const __nv_bfloat16* Xhi, const __nv_bfloat16* Xlo,
    const __nv_bfloat16* Whi, const __nv_bfloat16* Wlo)
{
#pragma unroll
    for (int it = 0; it < 4; it++) {
        int g = it * 256 + tid;
        int r = g >> 3, c = g & 7;
        uint32_t soff = (uint32_t)(r * APITCH_B + c * 16);
        size_t goff = (size_t)(row0 + r) * DMODEL + k0 + c * 8;
        CP_ASYNC16(st + SG_AHI + soff, Xhi + goff);
        CP_ASYNC16(st + SG_ALO + soff, Xlo + goff);
    }
#pragma unroll
    for (int it = 0; it < 2; it++) {
        int g = it * 256 + tid;
        int r = g >> 3, c = g & 7;
        uint32_t soff = (uint32_t)(r * APITCH_B + c * 16);
        size_t goff = (size_t)(col0 + r) * DMODEL + k0 + c * 8;
        CP_ASYNC16(st + SG_BHI + soff, Whi + goff);
        CP_ASYNC16(st + SG_BLO + soff, Wlo + goff);
    }
    CP_COMMIT();
}

__device__ __forceinline__ void gemm_main(
    GemmAcc& A, uint32_t sb, int tid, int row0, int col0,
    const __nv_bfloat16* Xhi, const __nv_bfloat16* Xlo,
    const __nv_bfloat16* Whi, const __nv_bfloat16* Wlo)
{
    const int wid = tid >> 5, lane = tid & 31;
    const int wm = wid >> 1, wn = wid & 1;

    gemm_load_stage(sb, tid, row0, col0, 0, Xhi, Xlo, Whi, Wlo);

    for (int ck = 0; ck < NKCH; ck++) {
        if (ck + 1 < NKCH) {
            gemm_load_stage(sb + (uint32_t)((ck + 1) & 1) * GEMM_STAGE,
                            tid, row0, col0, (ck + 1) * GKC, Xhi, Xlo, Whi, Wlo);
            CP_WAIT1();
        } else {
            CP_WAIT0();
        }
        __syncthreads();

        const uint32_t st = sb + (uint32_t)(ck & 1) * GEMM_STAGE;
#pragma unroll
        for (int s = 0; s < 4; s++) {
            const int kk = s * 16;
            uint32_t ah[2][4], al[2][4], bh[2][4], bl[2][4];
#pragma unroll
            for (int mf = 0; mf < 2; mf++) {
                int arow = wm * 32 + mf * 16 + (lane & 15);
                uint32_t off = (uint32_t)(arow * APITCH_B + (kk + ((lane >> 4) << 3)) * 2);
                LDSM4(ah[mf], st + SG_AHI + off);
                LDSM4(al[mf], st + SG_ALO + off);
            }
#pragma unroll
            for (int q = 0; q < 2; q++) {
                int brow = wn * 32 + q * 16 + ((lane >> 4) << 3) + (lane & 7);
                uint32_t off = (uint32_t)(brow * APITCH_B + (kk + (((lane >> 3) & 1) << 3)) * 2);
                LDSM4(bh[q], st + SG_BHI + off);
                LDSM4(bl[q], st + SG_BLO + off);
            }
#pragma unroll
            for (int mf = 0; mf < 2; mf++)
#pragma unroll
                for (int nf = 0; nf < 4; nf++) {
                    int q = nf >> 1, p = (nf & 1) << 1;
                    MMA_BF16(A.a[mf][nf], ah[mf], bh[q][p], bh[q][p+1]);
                    MMA_BF16(A.a[mf][nf], ah[mf], bl[q][p], bl[q][p+1]);
                    MMA_BF16(A.a[mf][nf], al[mf], bh[q][p], bh[q][p+1]);
                }
        }
        __syncthreads();
    }
}

// ---- fused QKV projection: grid (64, 36); y -> (mat, head) ----
__global__ __launch_bounds__(256, 2) void mma_qkv_kernel(
    const float* __restrict__ biasq, const float* __restrict__ biask,
    const float* __restrict__ biasv)
{
    extern __shared__ char smem[];
    const uint32_t sb = smem_u32(smem);
    const int tid = threadIdx.x;
    const int wid = tid >> 5, lane = tid & 31;
    const int wm = wid >> 1, wn = wid & 1;
    const int mat = blockIdx.y / NHEAD;          // 0=Q 1=K 2=V
    const int hh  = blockIdx.y % NHEAD;
    const int row0 = blockIdx.x * 128;
    const int col0 = hh * 64;
    const size_t WSZ = (size_t)DMODEL * DMODEL;

    const __nv_bfloat16* Whi = g_whi + (size_t)mat * WSZ;
    const __nv_bfloat16* Wlo = g_wlo + (size_t)mat * WSZ;
    const float* bias = (mat == 0) ? biasq : (mat == 1) ? biask : biasv;
    __nv_bfloat16* outHi = (mat == 0) ? g_qhi : (mat == 1) ? g_khi : g_vhi;
    __nv_bfloat16* outLo = (mat == 0) ? g_qlo : (mat == 1) ? g_klo : g_vlo;
    const float scale = (mat == 0) ? 0.125f : 1.0f;

    GemmAcc A = {};
    gemm_main(A, sb, tid, row0, col0, g_xhi, g_xlo, Whi, Wlo);

#pragma unroll
    for (int mf = 0; mf < 2; mf++)
#pragma unroll
        for (int nf = 0; nf < 4; nf++) {
            int colh = wn * 32 + nf * 8 + ((lane & 3) << 1);
            float2 bb = *(const float2*)&bias[col0 + colh];
#pragma unroll
            for (int hr = 0; hr < 2; hr++) {
                int n = row0 + wm * 32 + mf * 16 + (lane >> 2) + hr * 8;
                float vx = (A.a[mf][nf][hr*2+0] + bb.x) * scale;
                float vy = (A.a[mf][nf][hr*2+1] + bb.y) * scale;
                int b = n >> 12, sq = n & (SEQ - 1);
                size_t idx = (((size_t)(b * NHEAD + hh)) * SEQ + sq) * HDIM + colh;
                uint32_t hp = packbf(vx, vy);
                uint32_t lp = packbf(vx - lo16f(hp), vy - hi16f(hp));
                *(uint32_t*)&outHi[idx] = hp;
                *(uint32_t*)&outLo[idx] = lp;
            }
        }
}

// ---- output projection: preout splits (g_xhi/g_xlo) @ Wo^T + bo -> f32 ----
__global__ __launch_bounds__(256, 2) void mma_oproj_kernel(
    const float* __restrict__ bias, float* __restrict__ outF)
{
    extern __shared__ char smem[];
    const uint32_t sb = smem_u32(smem);
    const int tid = threadIdx.x;
    const int wid = tid >> 5, lane = tid & 31;
    const int wm = wid >> 1, wn = wid & 1;
    const int row0 = blockIdx.x * 128;
    const int col0 = blockIdx.y * 64;
    const size_t WSZ = (size_t)DMODEL * DMODEL;

    GemmAcc A = {};
    gemm_main(A, sb, tid, row0, col0, g_xhi, g_xlo, g_whi + 3*WSZ, g_wlo + 3*WSZ);

#pragma unroll
    for (int mf = 0; mf < 2; mf++)
#pragma unroll
        for (int nf = 0; nf < 4; nf++) {
            int colh = wn * 32 + nf * 8 + ((lane & 3) << 1);
            int col  = col0 + colh;
            float2 bb = *(const float2*)&bias[col];
#pragma unroll
            for (int hr = 0; hr < 2; hr++) {
                int n = row0 + wm * 32 + mf * 16 + (lane >> 2) + hr * 8;
                float2 v;
                v.x = A.a[mf][nf][hr*2+0] + bb.x;
                v.y = A.a[mf][nf][hr*2+1] + bb.y;
                *(float2*)&outF[(size_t)n * DMODEL + col] = v;
            }
        }
}

// =================================================================
// Tensor-core flash attention, causal. BQ=128, BK=64, 8 warps,
// 2 CTAs/SM (regs capped at 128; Q kept in persistent SMEM region and
// fragments re-read per s-step). 2-stage KV pipeline, lazy exp in PV.
// SMEM/CTA: Q region 36864 (Qhi +0, Qlo +18432), then 2 KV stages of
// 36864 (Khi +0, Klo +9216, Vhi +18432, Vlo +27648), pitch 144.
// =================================================================
#define FL_QREG  36864
#define FL_STAGE 36864
#define FL_SMEM  (FL_QREG + 2*FL_STAGE)   // 110592

__global__ __launch_bounds__(256, 2) void flash_tc_kernel()
{
    extern __shared__ char smemf[];
    const uint32_t qb = smem_u32(smemf);           // Q region
    const uint32_t kvb = qb + FL_QREG;             // KV stages
    const int tid = threadIdx.x;
    const int warp = tid >> 5, lane = tid & 31;
    const int qt = gridDim.x - 1 - blockIdx.x;     // longest CTAs first
    const int h = blockIdx.y, b = blockIdx.z;
    const size_t bh = (size_t)(b * NHEAD + h) * SEQ;
    const int q0 = qt * 128;

    // ---- stage Q tile into persistent region (group 0) ----
#pragma unroll
    for (int it = 0; it < 4; it++) {
        int g = it * 256 + tid;
        int r = g >> 3, c = g & 7;
        size_t src = (bh + q0 + r) * 64 + c * 8;
        uint32_t dst = qb + r * 144 + c * 16;
        CP_ASYNC16(dst,         g_qhi + src);
        CP_ASYNC16(dst + 18432, g_qlo + src);
    }
    CP_COMMIT();

    auto load_kv = [&](int key0, uint32_t st){
#pragma unroll
        for (int it = 0; it < 2; it++) {
            int g = it * 256 + tid;          // 0..511, 64 rows x 8 granules
            int r = g >> 3, c = g & 7;
            size_t src = (bh + key0 + r) * 64 + c * 8;
            uint32_t dst = st + r * 144 + c * 16;
            CP_ASYNC16(dst,         g_khi + src);
            CP_ASYNC16(dst +  9216, g_klo + src);
            CP_ASYNC16(dst + 18432, g_vhi + src);
            CP_ASYNC16(dst + 27648, g_vlo + src);
        }
        CP_COMMIT();
    };

    float O[8][4] = {};
    float mA = -1e30f, mB = -1e30f, lA = 0.f, lB = 0.f;

    const int nkt = 2 * qt + 2;                    // >= 2 always
    load_kv(0, kvb);                               // prologue: KV tile 0

    const int qr = warp * 16 + (lane & 15);

    for (int kt = 0; kt < nkt; kt++) {
        if (kt + 1 < nkt) {
            load_kv((kt + 1) * 64, kvb + (uint32_t)((kt + 1) & 1) * FL_STAGE);
            CP_WAIT1();    // retires Q (+KV_kt); leaves KV_{kt+1} in flight
        } else {
            CP_WAIT0();
        }
        __syncthreads();

        const uint32_t st = kvb + (uint32_t)(kt & 1) * FL_STAGE;
        const int key0 = kt * 64;

        // ---- S = (Q/8) K^T over 64 keys: 8 fragments; Q frags from SMEM ----
        float sacc[8][4] = {};
#pragma unroll
        for (int s = 0; s < 4; s++) {      // d 16-steps
            uint32_t qoff = (uint32_t)(qr * 144 + (s * 16 + ((lane >> 4) << 3)) * 2);
            uint32_t qhf[4], qlf[4];
            LDSM4(qhf, qb + qoff);
            LDSM4(qlf, qb + 18432 + qoff);
#pragma unroll
            for (int t = 0; t < 4; t++) {  // key 16-groups
                int brow = t * 16 + ((lane >> 4) << 3) + (lane & 7);
                uint32_t off = (uint32_t)(brow * 144 + (s * 16 + (((lane >> 3) & 1) << 3)) * 2);
                uint32_t kh[4], kl[4];
                LDSM4(kh, st + off);
                LDSM4(kl, st + 9216 + off);
                MMA_BF16(sacc[2*t],   qhf, kh[0], kh[1]);
                MMA_BF16(sacc[2*t],   qhf, kl[0], kl[1]);
                MMA_BF16(sacc[2*t],   qlf, kh[0], kh[1]);
                MMA_BF16(sacc[2*t+1], qhf, kh[2], kh[3]);
                MMA_BF16(sacc[2*t+1], qhf, kl[2], kl[3]);
                MMA_BF16(sacc[2*t+1], qlf, kh[2], kh[3]);
            }
        }

        // ---- causal mask (diagonal tiles: kt >= 2*qt) ----
        if (kt >= 2 * qt) {
            int rA = q0 + warp * 16 + (lane >> 2);
#pragma unroll
            for (int f = 0; f < 8; f++) {
                int cb = key0 + f * 8 + ((lane & 3) << 1);
                if (cb     > rA    ) sacc[f][0] = -1e30f;
                if (cb + 1 > rA    ) sacc[f][1] = -1e30f;
                if (cb     > rA + 8) sacc[f][2] = -1e30f;
                if (cb + 1 > rA + 8) sacc[f][3] = -1e30f;
            }
        }

        // ---- max reduce + O rescale (m-dependent serial part only) ----
        float mtA = -1e30f, mtB = -1e30f;
#pragma unroll
        for (int f = 0; f < 8; f++) {
            mtA = fmaxf(mtA, fmaxf(sacc[f][0], sacc[f][1]));
            mtB = fmaxf(mtB, fmaxf(sacc[f][2], sacc[f][3]));
        }
        mtA = fmaxf(mtA, __shfl_xor_sync(0xffffffffu, mtA, 1));
        mtA = fmaxf(mtA, __shfl_xor_sync(0xffffffffu, mtA, 2));
        mtB = fmaxf(mtB, __shfl_xor_sync(0xffffffffu, mtB, 1));
        mtB = fmaxf(mtB, __shfl_xor_sync(0xffffffffu, mtB, 2));
        float mnA = fmaxf(mA, mtA), mnB = fmaxf(mB, mtB);
        float aA = __expf(mA - mnA), aB = __expf(mB - mnB);
#pragma unroll
        for (int f = 0; f < 8; f++) {
            O[f][0] *= aA; O[f][1] *= aA; O[f][2] *= aB; O[f][3] *= aB;
        }

        // ---- O += P V with LAZY exp (MUFU hides under tensor MMAs) ----
        float rsA = 0.f, rsB = 0.f;
#pragma unroll
        for (int ks = 0; ks < 4; ks++) {
            uint32_t vbh[4][4], vbl[4][4];
            int vrow = ks * 16 + (((lane >> 3) & 1) << 3) + (lane & 7);
#pragma unroll
            for (int t = 0; t < 4; t++) {
                uint32_t off = (uint32_t)(vrow * 144 + (t * 16 + ((lane >> 4) << 3)) * 2);
                LDSM4T(vbh[t], st + 18432 + off);
                LDSM4T(vbl[t], st + 27648 + off);
            }
            float e00 = __expf(sacc[2*ks][0]   - mnA);
            float e01 = __expf(sacc[2*ks][1]   - mnA);
            float e02 = __expf(sacc[2*ks][2]   - mnB);
            float e03 = __expf(sacc[2*ks][3]   - mnB);
            float e10 = __expf(sacc[2*ks+1][0] - mnA);
            float e11 = __expf(sacc[2*ks+1][1] - mnA);
            float e12 = __expf(sacc[2*ks+1][2] - mnB);
            float e13 = __expf(sacc[2*ks+1][3] - mnB);
            rsA += (e00 + e01) + (e10 + e11);
            rsB += (e02 + e03) + (e12 + e13);
            uint32_t ph[4], pl[4];
            ph[0] = packbf(e00, e01); ph[1] = packbf(e02, e03);
            ph[2] = packbf(e10, e11); ph[3] = packbf(e12, e13);
            pl[0] = packbf(e00 - lo16f(ph[0]), e01 - hi16f(ph[0]));
            pl[1] = packbf(e02 - lo16f(ph[1]), e03 - hi16f(ph[1]));
            pl[2] = packbf(e10 - lo16f(ph[2]), e11 - hi16f(ph[2]));
            pl[3] = packbf(e12 - lo16f(ph[3]), e13 - hi16f(ph[3]));
#pragma unroll
            for (int f = 0; f < 8; f++) {
                int t = f >> 1, p = (f & 1) << 1;
                MMA_BF16(O[f], ph, vbh[t][p], vbh[t][p+1]);
                MMA_BF16(O[f], ph, vbl[t][p], vbl[t][p+1]);
                MMA_BF16(O[f], pl, vbh[t][p], vbh[t][p+1]);
            }
        }
        // fold row-sums (off critical path: once per tile)
        rsA += __shfl_xor_sync(0xffffffffu, rsA, 1);
        rsA += __shfl_xor_sync(0xffffffffu, rsA, 2);
        rsB += __shfl_xor_sync(0xffffffffu, rsB, 1);
        rsB += __shfl_xor_sync(0xffffffffu, rsB, 2);
        lA = lA * aA + rsA; mA = mnA;
        lB = lB * aB + rsB; mB = mnB;

        __syncthreads();   // done reading stage kt before it is refilled
    }

    // ---- epilogue: O/l, write preout splits into g_xhi/g_xlo ----
    float iA = __fdividef(1.f, lA), iB = __fdividef(1.f, lB);
    int rA = q0 + warp * 16 + (lane >> 2);
#pragma unroll
    for (int f = 0; f < 8; f++) {
        int colhd = f * 8 + ((lane & 3) << 1);
        size_t ia = ((size_t)b * SEQ + rA) * DMODEL + h * HDIM + colhd;
        size_t ib = ia + (size_t)8 * DMODEL;
        float x0 = O[f][0] * iA, x1 = O[f][1] * iA;
        float x2 = O[f][2] * iB, x3 = O[f][3] * iB;
        uint32_t hA = packbf(x0, x1);
        uint32_t lAw = packbf(x0 - lo16f(hA), x1 - hi16f(hA));
        uint32_t hB = packbf(x2, x3);
        uint32_t lBw = packbf(x2 - lo16f(hB), x3 - hi16f(hB));
        *(uint32_t*)&g_xhi[ia] = hA; *(uint32_t*)&g_xlo[ia] = lAw;
        *(uint32_t*)&g_xhi[ib] = hB; *(uint32_t*)&g_xlo[ib] = lBw;
    }
}

// =================================================================
extern "C" void kernel_launch(void* const* d_in, const int* in_sizes, int n_in,
                              void* d_out, int out_size)
{
    (void)in_sizes; (void)n_in; (void)out_size;
    const float* x  = (const float*)d_in[0];
    const float* Wq = (const float*)d_in[1];
    const float* bq = (const float*)d_in[2];
    const float* Wk = (const float*)d_in[3];
    const float* bk = (const float*)d_in[4];
    const float* Wv = (const float*)d_in[5];
    const float* bv = (const float*)d_in[6];
    const float* Wo = (const float*)d_in[7];
    const float* bo = (const float*)d_in[8];
    float* out = (float*)d_out;

    void *pxh, *pxl;
    cudaGetSymbolAddress(&pxh, g_xhi); cudaGetSymbolAddress(&pxl, g_xlo);
    __nv_bfloat16* xhi = (__nv_bfloat16*)pxh;
    __nv_bfloat16* xlo = (__nv_bfloat16*)pxl;

    cudaFuncSetAttribute(mma_qkv_kernel,
                         cudaFuncAttributeMaxDynamicSharedMemorySize, GEMM_SMEM);
    cudaFuncSetAttribute(mma_oproj_kernel,
                         cudaFuncAttributeMaxDynamicSharedMemorySize, GEMM_SMEM);
    cudaFuncSetAttribute(flash_tc_kernel,
                         cudaFuncAttributeMaxDynamicSharedMemorySize, FL_SMEM);

    // ---- split conversions ----
    const int XN4 = NTOK * DMODEL / 4;
    const int WN4 = (int)((size_t)DMODEL * DMODEL / 4);
    split_kernel<<<XN4 / 256, 256>>>(x, xhi, xlo, XN4);
    dim3 gw(WN4 / 256, 4);
    split_w4_kernel<<<gw, 256>>>(Wq, Wk, Wv, Wo, WN4);

    // ---- fused QKV projection ----
    dim3 gq(NTOK / 128, 3 * NHEAD);        // 64 x 36
    mma_qkv_kernel<<<gq, 256, GEMM_SMEM>>>(bq, bk, bv);

    // ---- tensor-core flash attention (writes preout splits to xhi/xlo) ----
    dim3 gf(SEQ / 128, NHEAD, BATCH);      // 32 x 12 x 2
    flash_tc_kernel<<<gf, 256, FL_SMEM>>>();

    // ---- output projection ----
    dim3 go(NTOK / 128, DMODEL / 64);      // 64 x 12
    mma_oproj_kernel<<<go, 256, GEMM_SMEM>>>(bo, out);
}

// round 17
// speedup vs baseline: 1.0799x; 1.0799x over previous
#include <cuda_runtime.h>
#include <cuda_bf16.h>
#include <cuda_fp16.h>
#include <math.h>
#include <stdint.h>

#define BATCH 2
#define SEQ   4096
#define DMODEL 768
#define NHEAD 12
#define HDIM  64
#define NTOK  (BATCH*SEQ)   // 8192

// ---------------- scratch (no allocations allowed) ----------------
__device__ __nv_bfloat16 g_qhi[(size_t)BATCH*NHEAD*SEQ*HDIM];  // [B,H,S,64], pre-scaled 1/8
__device__ __nv_bfloat16 g_qlo[(size_t)BATCH*NHEAD*SEQ*HDIM];
__device__ __nv_bfloat16 g_khi[(size_t)BATCH*NHEAD*SEQ*HDIM];
__device__ __nv_bfloat16 g_klo[(size_t)BATCH*NHEAD*SEQ*HDIM];
__device__ __half        g_vhi[(size_t)BATCH*NHEAD*SEQ*HDIM];  // fp16 split for PV
__device__ __half        g_vlo[(size_t)BATCH*NHEAD*SEQ*HDIM];

__device__ __nv_bfloat16 g_xhi[(size_t)NTOK*DMODEL];   // x splits; later reused for preout splits
__device__ __nv_bfloat16 g_xlo[(size_t)NTOK*DMODEL];
__device__ __nv_bfloat16 g_whi[4*(size_t)DMODEL*DMODEL];
__device__ __nv_bfloat16 g_wlo[4*(size_t)DMODEL*DMODEL];

// ================= portable (sm_80+) asm helpers =================
__device__ __forceinline__ uint32_t smem_u32(const void* p){
    uint32_t a;
    asm("{ .reg .u64 t; cvta.to.shared.u64 t, %1; cvt.u32.u64 %0, t; }" : "=r"(a) : "l"(p));
    return a;
}

#define CP_ASYNC16(dst, src) \
    asm volatile("cp.async.cg.shared.global [%0], [%1], 16;" :: "r"(dst), "l"(src))
#define CP_COMMIT()  asm volatile("cp.async.commit_group;" ::: "memory")
#define CP_WAIT0()   asm volatile("cp.async.wait_group 0;" ::: "memory")
#define CP_WAIT1()   asm volatile("cp.async.wait_group 1;" ::: "memory")

#define LDSM4(r, addr) \
    asm volatile("ldmatrix.sync.aligned.m8n8.x4.shared.b16 {%0,%1,%2,%3}, [%4];" \
        : "=r"((r)[0]), "=r"((r)[1]), "=r"((r)[2]), "=r"((r)[3]) : "r"(addr))

#define LDSM4T(r, addr) \
    asm volatile("ldmatrix.sync.aligned.m8n8.x4.trans.shared.b16 {%0,%1,%2,%3}, [%4];" \
        : "=r"((r)[0]), "=r"((r)[1]), "=r"((r)[2]), "=r"((r)[3]) : "r"(addr))

#define MMA_BF16(d, a, b0, b1) \
    asm volatile("mma.sync.aligned.m16n8k16.row.col.f32.bf16.bf16.f32 " \
        "{%0,%1,%2,%3}, {%4,%5,%6,%7}, {%8,%9}, {%0,%1,%2,%3};" \
        : "+f"((d)[0]), "+f"((d)[1]), "+f"((d)[2]), "+f"((d)[3]) \
        : "r"((a)[0]), "r"((a)[1]), "r"((a)[2]), "r"((a)[3]), "r"(b0), "r"(b1))

#define MMA_F16(d, a, b0, b1) \
    asm volatile("mma.sync.aligned.m16n8k16.row.col.f32.f16.f16.f32 " \
        "{%0,%1,%2,%3}, {%4,%5,%6,%7}, {%8,%9}, {%0,%1,%2,%3};" \
        : "+f"((d)[0]), "+f"((d)[1]), "+f"((d)[2]), "+f"((d)[3]) \
        : "r"((a)[0]), "r"((a)[1]), "r"((a)[2]), "r"((a)[3]), "r"(b0), "r"(b1))

__device__ __forceinline__ uint32_t packbf(float lo, float hi){
    uint32_t r;
    asm("cvt.rn.bf16x2.f32 %0, %1, %2;" : "=r"(r) : "f"(hi), "f"(lo));
    return r;
}
__device__ __forceinline__ uint32_t packhf(float lo, float hi){
    uint32_t r;
    asm("cvt.rn.f16x2.f32 %0, %1, %2;" : "=r"(r) : "f"(hi), "f"(lo));
    return r;
}
__device__ __forceinline__ float lo16f(uint32_t p){ return __uint_as_float(p << 16); }
__device__ __forceinline__ float hi16f(uint32_t p){ return __uint_as_float(p & 0xffff0000u); }

// =================================================================
// split kernels
// =================================================================
__global__ void split_kernel(const float* __restrict__ in,
                             __nv_bfloat16* __restrict__ hi,
                             __nv_bfloat16* __restrict__ lo, int n4)
{
    int i = blockIdx.x * blockDim.x + threadIdx.x;
    if (i >= n4) return;
    float4 v = ((const float4*)in)[i];
    uint32_t h0 = packbf(v.x, v.y);
    uint32_t h1 = packbf(v.z, v.w);
    uint32_t l0 = packbf(v.x - lo16f(h0), v.y - hi16f(h0));
    uint32_t l1 = packbf(v.z - lo16f(h1), v.w - hi16f(h1));
    ((uint32_t*)hi)[2*i]   = h0;
    ((uint32_t*)hi)[2*i+1] = h1;
    ((uint32_t*)lo)[2*i]   = l0;
    ((uint32_t*)lo)[2*i+1] = l1;
}

// fused 4-weight split: blockIdx.y selects matrix; outputs at mat*WSZ
__global__ void split_w4_kernel(const float* __restrict__ w0, const float* __restrict__ w1,
                                const float* __restrict__ w2, const float* __restrict__ w3,
                                int n4)
{
    int i = blockIdx.x * blockDim.x + threadIdx.x;
    if (i >= n4) return;
    int mat = blockIdx.y;
    const float* in = (mat == 0) ? w0 : (mat == 1) ? w1 : (mat == 2) ? w2 : w3;
    const size_t WSZ = (size_t)DMODEL * DMODEL;
    __nv_bfloat16* hi = g_whi + (size_t)mat * WSZ;
    __nv_bfloat16* lo = g_wlo + (size_t)mat * WSZ;
    float4 v = ((const float4*)in)[i];
    uint32_t h0 = packbf(v.x, v.y);
    uint32_t h1 = packbf(v.z, v.w);
    uint32_t l0 = packbf(v.x - lo16f(h0), v.y - hi16f(h0));
    uint32_t l1 = packbf(v.z - lo16f(h1), v.w - hi16f(h1));
    ((uint32_t*)hi)[2*i]   = h0;
    ((uint32_t*)hi)[2*i+1] = h1;
    ((uint32_t*)lo)[2*i]   = l0;
    ((uint32_t*)lo)[2*i+1] = l1;
}

// =================================================================
// GEMM core machinery (shared by QKV-fused and out-proj kernels)
// CTA tile 128x64, 8 warps (4m x 2n), K-chunks of 64, 2-stage pipe.
// =================================================================
#define GKC 64
#define NKCH (DMODEL/GKC)          // 12
#define APITCH_B 144

#define SG_AHI 0
#define SG_ALO 18432
#define SG_BHI 36864
#define SG_BLO 46080
#define GEMM_STAGE 55296
#define GEMM_SMEM  (2*GEMM_STAGE)  // 110592

struct GemmAcc { float a[2][4][4]; };

__device__ __forceinline__ void gemm_load_stage(
    uint32_t st, int tid, int row0, int col0, int k0,
    const __nv_bfloat16* Xhi, const __nv_bfloat16* Xlo,
    const __nv_bfloat16* Whi, const __nv_bfloat16* Wlo)
{
#pragma unroll
    for (int it = 0; it < 4; it++) {
        int g = it * 256 + tid;
        int r = g >> 3, c = g & 7;
        uint32_t soff = (uint32_t)(r * APITCH_B + c * 16);
        size_t goff = (size_t)(row0 + r) * DMODEL + k0 + c * 8;
        CP_ASYNC16(st + SG_AHI + soff, Xhi + goff);
        CP_ASYNC16(st + SG_ALO + soff, Xlo + goff);
    }
#pragma unroll
    for (int it = 0; it < 2; it++) {
        int g = it * 256 + tid;
        int r = g >> 3, c = g & 7;
        uint32_t soff = (uint32_t)(r * APITCH_B + c * 16);
        size_t goff = (size_t)(col0 + r) * DMODEL + k0 + c * 8;
        CP_ASYNC16(st + SG_BHI + soff, Whi + goff);
        CP_ASYNC16(st + SG_BLO + soff, Wlo + goff);
    }
    CP_COMMIT();
}

__device__ __forceinline__ void gemm_main(
    GemmAcc& A, uint32_t sb, int tid, int row0, int col0,
    const __nv_bfloat16* Xhi, const __nv_bfloat16* Xlo,
    const __nv_bfloat16* Whi, const __nv_bfloat16* Wlo)
{
    const int wid = tid >> 5, lane = tid & 31;
    const int wm = wid >> 1, wn = wid & 1;

    gemm_load_stage(sb, tid, row0, col0, 0, Xhi, Xlo, Whi, Wlo);

    for (int ck = 0; ck < NKCH; ck++) {
        if (ck + 1 < NKCH) {
            gemm_load_stage(sb + (uint32_t)((ck + 1) & 1) * GEMM_STAGE,
                            tid, row0, col0, (ck + 1) * GKC, Xhi, Xlo, Whi, Wlo);
            CP_WAIT1();
        } else {
            CP_WAIT0();
        }
        __syncthreads();

        const uint32_t st = sb + (uint32_t)(ck & 1) * GEMM_STAGE;
#pragma unroll
        for (int s = 0; s < 4; s++) {
            const int kk = s * 16;
            uint32_t ah[2][4], al[2][4], bh[2][4], bl[2][4];
#pragma unroll
            for (int mf = 0; mf < 2; mf++) {
                int arow = wm * 32 + mf * 16 + (lane & 15);
                uint32_t off = (uint32_t)(arow * APITCH_B + (kk + ((lane >> 4) << 3)) * 2);
                LDSM4(ah[mf], st + SG_AHI + off);
                LDSM4(al[mf], st + SG_ALO + off);
            }
#pragma unroll
            for (int q = 0; q < 2; q++) {
                int brow = wn * 32 + q * 16 + ((lane >> 4) << 3) + (lane & 7);
                uint32_t off = (uint32_t)(brow * APITCH_B + (kk + (((lane >> 3) & 1) << 3)) * 2);
                LDSM4(bh[q], st + SG_BHI + off);
                LDSM4(bl[q], st + SG_BLO + off);
            }
#pragma unroll
            for (int mf = 0; mf < 2; mf++)
#pragma unroll
                for (int nf = 0; nf < 4; nf++) {
                    int q = nf >> 1, p = (nf & 1) << 1;
                    MMA_BF16(A.a[mf][nf], ah[mf], bh[q][p], bh[q][p+1]);
                    MMA_BF16(A.a[mf][nf], ah[mf], bl[q][p], bl[q][p+1]);
                    MMA_BF16(A.a[mf][nf], al[mf], bh[q][p], bh[q][p+1]);
                }
        }
        __syncthreads();
    }
}

// ---- fused QKV projection: grid (64, 36); y -> (mat, head) ----
// Q/K written as bf16 hi/lo splits; V written as fp16 hi/lo splits.
__global__ __launch_bounds__(256, 2) void mma_qkv_kernel(
    const float* __restrict__ biasq, const float* __restrict__ biask,
    const float* __restrict__ biasv)
{
    extern __shared__ char smem[];
    const uint32_t sb = smem_u32(smem);
    const int tid = threadIdx.x;
    const int wid = tid >> 5, lane = tid & 31;
    const int wm = wid >> 1, wn = wid & 1;
    const int mat = blockIdx.y / NHEAD;          // 0=Q 1=K 2=V
    const int hh  = blockIdx.y % NHEAD;
    const int row0 = blockIdx.x * 128;
    const int col0 = hh * 64;
    const size_t WSZ = (size_t)DMODEL * DMODEL;

    const __nv_bfloat16* Whi = g_whi + (size_t)mat * WSZ;
    const __nv_bfloat16* Wlo = g_wlo + (size_t)mat * WSZ;
    const float* bias = (mat == 0) ? biasq : (mat == 1) ? biask : biasv;
    const float scale = (mat == 0) ? 0.125f : 1.0f;

    GemmAcc A = {};
    gemm_main(A, sb, tid, row0, col0, g_xhi, g_xlo, Whi, Wlo);

#pragma unroll
    for (int mf = 0; mf < 2; mf++)
#pragma unroll
        for (int nf = 0; nf < 4; nf++) {
            int colh = wn * 32 + nf * 8 + ((lane & 3) << 1);
            float2 bb = *(const float2*)&bias[col0 + colh];
#pragma unroll
            for (int hr = 0; hr < 2; hr++) {
                int n = row0 + wm * 32 + mf * 16 + (lane >> 2) + hr * 8;
                float vx = (A.a[mf][nf][hr*2+0] + bb.x) * scale;
                float vy = (A.a[mf][nf][hr*2+1] + bb.y) * scale;
                int b = n >> 12, sq = n & (SEQ - 1);
                size_t idx = (((size_t)(b * NHEAD + hh)) * SEQ + sq) * HDIM + colh;
                if (mat == 2) {
                    // fp16 split for V
                    __half hx = __float2half_rn(vx), hy = __float2half_rn(vy);
                    float rx = vx - __half2float(hx), ry = vy - __half2float(hy);
                    uint32_t hp = packhf(__half2float(hx), __half2float(hy));
                    uint32_t lp = packhf(rx, ry);
                    *(uint32_t*)&g_vhi[idx] = hp;
                    *(uint32_t*)&g_vlo[idx] = lp;
                } else {
                    __nv_bfloat16* outHi = (mat == 0) ? g_qhi : g_khi;
                    __nv_bfloat16* outLo = (mat == 0) ? g_qlo : g_klo;
                    uint32_t hp = packbf(vx, vy);
                    uint32_t lp = packbf(vx - lo16f(hp), vy - hi16f(hp));
                    *(uint32_t*)&outHi[idx] = hp;
                    *(uint32_t*)&outLo[idx] = lp;
                }
            }
        }
}

// ---- output projection: preout splits (g_xhi/g_xlo) @ Wo^T + bo -> f32 ----
__global__ __launch_bounds__(256, 2) void mma_oproj_kernel(
    const float* __restrict__ bias, float* __restrict__ outF)
{
    extern __shared__ char smem[];
    const uint32_t sb = smem_u32(smem);
    const int tid = threadIdx.x;
    const int wid = tid >> 5, lane = tid & 31;
    const int wm = wid >> 1, wn = wid & 1;
    const int row0 = blockIdx.x * 128;
    const int col0 = blockIdx.y * 64;
    const size_t WSZ = (size_t)DMODEL * DMODEL;

    GemmAcc A = {};
    gemm_main(A, sb, tid, row0, col0, g_xhi, g_xlo, g_whi + 3*WSZ, g_wlo + 3*WSZ);

#pragma unroll
    for (int mf = 0; mf < 2; mf++)
#pragma unroll
        for (int nf = 0; nf < 4; nf++) {
            int colh = wn * 32 + nf * 8 + ((lane & 3) << 1);
            int col  = col0 + colh;
            float2 bb = *(const float2*)&bias[col];
#pragma unroll
            for (int hr = 0; hr < 2; hr++) {
                int n = row0 + wm * 32 + mf * 16 + (lane >> 2) + hr * 8;
                float2 v;
                v.x = A.a[mf][nf][hr*2+0] + bb.x;
                v.y = A.a[mf][nf][hr*2+1] + bb.y;
                *(float2*)&outF[(size_t)n * DMODEL + col] = v;
            }
        }
}

// =================================================================
// Tensor-core flash attention, causal. BQ=128, BK=64, 8 warps,
// 2 CTAs/SM. S = bf16 3-MMA split (exact); PV = fp16, P single (no lo),
// V hi/lo fp16 split -> 2 MMAs. Lazy exp in PV loop.
// SMEM/CTA: Q region 36864 (Qhi +0, Qlo +18432), then 2 KV stages of
// 36864 (Khi +0, Klo +9216, Vhi +18432, Vlo +27648), pitch 144.
// =================================================================
#define FL_QREG  36864
#define FL_STAGE 36864
#define FL_SMEM  (FL_QREG + 2*FL_STAGE)   // 110592

__global__ __launch_bounds__(256, 2) void flash_tc_kernel()
{
    extern __shared__ char smemf[];
    const uint32_t qb = smem_u32(smemf);           // Q region
    const uint32_t kvb = qb + FL_QREG;             // KV stages
    const int tid = threadIdx.x;
    const int warp = tid >> 5, lane = tid & 31;
    const int qt = gridDim.x - 1 - blockIdx.x;     // longest CTAs first
    const int h = blockIdx.y, b = blockIdx.z;
    const size_t bh = (size_t)(b * NHEAD + h) * SEQ;
    const int q0 = qt * 128;

    // ---- stage Q tile into persistent region (group 0) ----
#pragma unroll
    for (int it = 0; it < 4; it++) {
        int g = it * 256 + tid;
        int r = g >> 3, c = g & 7;
        size_t src = (bh + q0 + r) * 64 + c * 8;
        uint32_t dst = qb + r * 144 + c * 16;
        CP_ASYNC16(dst,         g_qhi + src);
        CP_ASYNC16(dst + 18432, g_qlo + src);
    }
    CP_COMMIT();

    auto load_kv = [&](int key0, uint32_t st){
#pragma unroll
        for (int it = 0; it < 2; it++) {
            int g = it * 256 + tid;          // 0..511, 64 rows x 8 granules
            int r = g >> 3, c = g & 7;
            size_t src = (bh + key0 + r) * 64 + c * 8;
            uint32_t dst = st + r * 144 + c * 16;
            CP_ASYNC16(dst,         g_khi + src);
            CP_ASYNC16(dst +  9216, g_klo + src);
            CP_ASYNC16(dst + 18432, g_vhi + src);
            CP_ASYNC16(dst + 27648, g_vlo + src);
        }
        CP_COMMIT();
    };

    float O[8][4] = {};
    float mA = -1e30f, mB = -1e30f, lA = 0.f, lB = 0.f;

    const int nkt = 2 * qt + 2;                    // >= 2 always
    load_kv(0, kvb);                               // prologue: KV tile 0

    const int qr = warp * 16 + (lane & 15);

    for (int kt = 0; kt < nkt; kt++) {
        if (kt + 1 < nkt) {
            load_kv((kt + 1) * 64, kvb + (uint32_t)((kt + 1) & 1) * FL_STAGE);
            CP_WAIT1();    // retires Q (+KV_kt); leaves KV_{kt+1} in flight
        } else {
            CP_WAIT0();
        }
        __syncthreads();

        const uint32_t st = kvb + (uint32_t)(kt & 1) * FL_STAGE;
        const int key0 = kt * 64;

        // ---- S = (Q/8) K^T over 64 keys: 8 fragments; Q frags from SMEM ----
        float sacc[8][4] = {};
#pragma unroll
        for (int s = 0; s < 4; s++) {      // d 16-steps
            uint32_t qoff = (uint32_t)(qr * 144 + (s * 16 + ((lane >> 4) << 3)) * 2);
            uint32_t qhf[4], qlf[4];
            LDSM4(qhf, qb + qoff);
            LDSM4(qlf, qb + 18432 + qoff);
#pragma unroll
            for (int t = 0; t < 4; t++) {  // key 16-groups
                int brow = t * 16 + ((lane >> 4) << 3) + (lane & 7);
                uint32_t off = (uint32_t)(brow * 144 + (s * 16 + (((lane >> 3) & 1) << 3)) * 2);
                uint32_t kh[4], kl[4];
                LDSM4(kh, st + off);
                LDSM4(kl, st + 9216 + off);
                MMA_BF16(sacc[2*t],   qhf, kh[0], kh[1]);
                MMA_BF16(sacc[2*t],   qhf, kl[0], kl[1]);
                MMA_BF16(sacc[2*t],   qlf, kh[0], kh[1]);
                MMA_BF16(sacc[2*t+1], qhf, kh[2], kh[3]);
                MMA_BF16(sacc[2*t+1], qhf, kl[2], kl[3]);
                MMA_BF16(sacc[2*t+1], qlf, kh[2], kh[3]);
            }
        }

        // ---- causal mask (diagonal tiles: kt >= 2*qt) ----
        if (kt >= 2 * qt) {
            int rA = q0 + warp * 16 + (lane >> 2);
#pragma unroll
            for (int f = 0; f < 8; f++) {
                int cb = key0 + f * 8 + ((lane & 3) << 1);
                if (cb     > rA    ) sacc[f][0] = -1e30f;
                if (cb + 1 > rA    ) sacc[f][1] = -1e30f;
                if (cb     > rA + 8) sacc[f][2] = -1e30f;
                if (cb + 1 > rA + 8) sacc[f][3] = -1e30f;
            }
        }

        // ---- max reduce + O rescale (m-dependent serial part only) ----
        float mtA = -1e30f, mtB = -1e30f;
#pragma unroll
        for (int f = 0; f < 8; f++) {
            mtA = fmaxf(mtA, fmaxf(sacc[f][0], sacc[f][1]));
            mtB = fmaxf(mtB, fmaxf(sacc[f][2], sacc[f][3]));
        }
        mtA = fmaxf(mtA, __shfl_xor_sync(0xffffffffu, mtA, 1));
        mtA = fmaxf(mtA, __shfl_xor_sync(0xffffffffu, mtA, 2));
        mtB = fmaxf(mtB, __shfl_xor_sync(0xffffffffu, mtB, 1));
        mtB = fmaxf(mtB, __shfl_xor_sync(0xffffffffu, mtB, 2));
        float mnA = fmaxf(mA, mtA), mnB = fmaxf(mB, mtB);
        float aA = __expf(mA - mnA), aB = __expf(mB - mnB);
#pragma unroll
        for (int f = 0; f < 8; f++) {
            O[f][0] *= aA; O[f][1] *= aA; O[f][2] *= aB; O[f][3] *= aB;
        }

        // ---- O += P V : fp16 P (single) x fp16 V (hi+lo), lazy exp ----
        float rsA = 0.f, rsB = 0.f;
#pragma unroll
        for (int ks = 0; ks < 4; ks++) {
            uint32_t vbh[4][4], vbl[4][4];
            int vrow = ks * 16 + (((lane >> 3) & 1) << 3) + (lane & 7);
#pragma unroll
            for (int t = 0; t < 4; t++) {
                uint32_t off = (uint32_t)(vrow * 144 + (t * 16 + ((lane >> 4) << 3)) * 2);
                LDSM4T(vbh[t], st + 18432 + off);
                LDSM4T(vbl[t], st + 27648 + off);
            }
            float e00 = __expf(sacc[2*ks][0]   - mnA);
            float e01 = __expf(sacc[2*ks][1]   - mnA);
            float e02 = __expf(sacc[2*ks][2]   - mnB);
            float e03 = __expf(sacc[2*ks][3]   - mnB);
            float e10 = __expf(sacc[2*ks+1][0] - mnA);
            float e11 = __expf(sacc[2*ks+1][1] - mnA);
            float e12 = __expf(sacc[2*ks+1][2] - mnB);
            float e13 = __expf(sacc[2*ks+1][3] - mnB);
            rsA += (e00 + e01) + (e10 + e11);
            rsB += (e02 + e03) + (e12 + e13);
            uint32_t ph[4];
            ph[0] = packhf(e00, e01); ph[1] = packhf(e02, e03);
            ph[2] = packhf(e10, e11); ph[3] = packhf(e12, e13);
#pragma unroll
            for (int f = 0; f < 8; f++) {
                int t = f >> 1, p = (f & 1) << 1;
                MMA_F16(O[f], ph, vbh[t][p], vbh[t][p+1]);
                MMA_F16(O[f], ph, vbl[t][p], vbl[t][p+1]);
            }
        }
        // fold row-sums (off critical path: once per tile)
        rsA += __shfl_xor_sync(0xffffffffu, rsA, 1);
        rsA += __shfl_xor_sync(0xffffffffu, rsA, 2);
        rsB += __shfl_xor_sync(0xffffffffu, rsB, 1);
        rsB += __shfl_xor_sync(0xffffffffu, rsB, 2);
        lA = lA * aA + rsA; mA = mnA;
        lB = lB * aB + rsB; mB = mnB;

        __syncthreads();   // done reading stage kt before it is refilled
    }

    // ---- epilogue: O/l, write preout splits into g_xhi/g_xlo ----
    float iA = __fdividef(1.f, lA), iB = __fdividef(1.f, lB);
    int rA = q0 + warp * 16 + (lane >> 2);
#pragma unroll
    for (int f = 0; f < 8; f++) {
        int colhd = f * 8 + ((lane & 3) << 1);
        size_t ia = ((size_t)b * SEQ + rA) * DMODEL + h * HDIM + colhd;
        size_t ib = ia + (size_t)8 * DMODEL;
        float x0 = O[f][0] * iA, x1 = O[f][1] * iA;
        float x2 = O[f][2] * iB, x3 = O[f][3] * iB;
        uint32_t hA = packbf(x0, x1);
        uint32_t lAw = packbf(x0 - lo16f(hA), x1 - hi16f(hA));
        uint32_t hB = packbf(x2, x3);
        uint32_t lBw = packbf(x2 - lo16f(hB), x3 - hi16f(hB));
        *(uint32_t*)&g_xhi[ia] = hA; *(uint32_t*)&g_xlo[ia] = lAw;
        *(uint32_t*)&g_xhi[ib] = hB; *(uint32_t*)&g_xlo[ib] = lBw;
    }
}

// =================================================================
extern "C" void kernel_launch(void* const* d_in, const int* in_sizes, int n_in,
                              void* d_out, int out_size)
{
    (void)in_sizes; (void)n_in; (void)out_size;
    const float* x  = (const float*)d_in[0];
    const float* Wq = (const float*)d_in[1];
    const float* bq = (const float*)d_in[2];
    const float* Wk = (const float*)d_in[3];
    const float* bk = (const float*)d_in[4];
    const float* Wv = (const float*)d_in[5];
    const float* bv = (const float*)d_in[6];
    const float* Wo = (const float*)d_in[7];
    const float* bo = (const float*)d_in[8];
    float* out = (float*)d_out;

    void *pxh, *pxl;
    cudaGetSymbolAddress(&pxh, g_xhi); cudaGetSymbolAddress(&pxl, g_xlo);
    __nv_bfloat16* xhi = (__nv_bfloat16*)pxh;
    __nv_bfloat16* xlo = (__nv_bfloat16*)pxl;

    cudaFuncSetAttribute(mma_qkv_kernel,
                         cudaFuncAttributeMaxDynamicSharedMemorySize, GEMM_SMEM);
    cudaFuncSetAttribute(mma_oproj_kernel,
                         cudaFuncAttributeMaxDynamicSharedMemorySize, GEMM_SMEM);
    cudaFuncSetAttribute(flash_tc_kernel,
                         cudaFuncAttributeMaxDynamicSharedMemorySize, FL_SMEM);

    // ---- split conversions ----
    const int XN4 = NTOK * DMODEL / 4;
    const int WN4 = (int)((size_t)DMODEL * DMODEL / 4);
    split_kernel<<<XN4 / 256, 256>>>(x, xhi, xlo, XN4);
    dim3 gw(WN4 / 256, 4);
    split_w4_kernel<<<gw, 256>>>(Wq, Wk, Wv, Wo, WN4);

    // ---- fused QKV projection ----
    dim3 gq(NTOK / 128, 3 * NHEAD);        // 64 x 36
    mma_qkv_kernel<<<gq, 256, GEMM_SMEM>>>(bq, bk, bv);

    // ---- tensor-core flash attention (writes preout splits to xhi/xlo) ----
    dim3 gf(SEQ / 128, NHEAD, BATCH);      // 32 x 12 x 2
    flash_tc_kernel<<<gf, 256, FL_SMEM>>>();

    // ---- output projection ----
    dim3 go(NTOK / 128, DMODEL / 64);      // 64 x 12
    mma_oproj_kernel<<<go, 256, GEMM_SMEM>>>(bo, out);
}